// round 1
// baseline (speedup 1.0000x reference)
#include <cuda_runtime.h>
#include <cstdint>

#define BATCH 4
#define SEQ   2048
#define CDIM  2048
#define NH    16
#define DK    128
#define BH    (BATCH*NH)          /* 64  */
#define BTC   (BATCH*SEQ*CDIM)    /* 16777216 */

// Scratch (static device arrays: sanctioned scratch mechanism, no allocs)
__device__ float g_Q [(size_t)BH*SEQ*DK];     // Q in [b,h,t,d]   (64 MB)
__device__ float g_VT[(size_t)BH*DK*SEQ];     // V^T in [b,h,d,t] (64 MB)
__device__ float g_S [(size_t)BH*SEQ*SEQ];    // scores/probs     (1 GB)
__device__ float g_Y [(size_t)BATCH*SEQ*CDIM];// attn out [b,t,c] (64 MB)

__device__ __forceinline__ unsigned f2tf(float f){
    unsigned u; asm("cvt.rna.tf32.f32 %0, %1;" : "=r"(u) : "f"(f)); return u;
}

__device__ __forceinline__ void mma8(float* c, const unsigned* a, const unsigned* b){
    asm volatile("mma.sync.aligned.m16n8k8.row.col.f32.tf32.tf32.f32 "
        "{%0,%1,%2,%3}, {%4,%5,%6,%7}, {%8,%9}, {%0,%1,%2,%3};\n"
        : "+f"(c[0]), "+f"(c[1]), "+f"(c[2]), "+f"(c[3])
        : "r"(a[0]), "r"(a[1]), "r"(a[2]), "r"(a[3]), "r"(b[0]), "r"(b[1]));
}

// Generic D[M,N] = A[M,K] @ B[N,K]^T, tf32 MMA, 128x128x32 tiles, 256 threads.
// MODE 0: QKV   (A=x, B=w_attn)  epilogue: +bias, scatter Q/K/V (+V^T)
// MODE 1: QK^T  (per-head via bz) epilogue: *1/sqrt(dk) -> S ; skip bx>by
// MODE 2: P V   (per-head via bz) K clipped to (by+1)*128 ; -> Y[b,t,c]
// MODE 3: proj  epilogue: +bias -> y out
template<int MODE>
__global__ void __launch_bounds__(256, 1)
gemm_tf32(const float* __restrict__ Ag, const float* __restrict__ Bg,
          const float* __restrict__ bias,
          float* __restrict__ O0, float* __restrict__ O1,
          float* __restrict__ O2, float* __restrict__ O3,
          int M, int N, int K, int lda, int ldb)
{
    const int bx = blockIdx.x, by = blockIdx.y, bz = blockIdx.z;
    if (MODE == 1 && bx > by) return;   // causal: upper-triangle tiles never read

    const float* A  = Ag;
    const float* Bm = Bg;
    if (MODE == 1){ A += (size_t)bz*SEQ*DK;  Bm += (size_t)bz*SEQ*DK; }
    if (MODE == 2){ A += (size_t)bz*SEQ*SEQ; Bm += (size_t)bz*DK*SEQ; K = (by+1)*128; }

    extern __shared__ unsigned smbuf[];
    unsigned* sA = smbuf;          // [2][128][32] tf32 words
    unsigned* sB = smbuf + 8192;   // [2][128][32]

    const int tid  = threadIdx.x;
    const int lane = tid & 31, warp = tid >> 5;
    const int wr = warp >> 1, wc = warp & 1;      // warp grid 4x2 -> tile 32x64
    const int lr = lane >> 2, lk = lane & 3;
    const int mBase = by*128, nBase = bx*128;
    const int gr = tid >> 3, k4 = tid & 7;        // g2s: row=gr+i*32, float4 col=k4
    const int sw = k4 ^ (gr & 7);                 // xor swizzle @float4 granularity

    float acc[2][8][4];
    #pragma unroll
    for (int mt=0; mt<2; ++mt)
      #pragma unroll
      for (int nt=0; nt<8; ++nt)
        #pragma unroll
        for (int i=0; i<4; ++i) acc[mt][nt][i] = 0.f;

    uint4 stA[4], stB[4];
    const int KT = K >> 5;

    // prologue: stage 0
    #pragma unroll
    for (int i=0; i<4; ++i){
        float4 va = *(const float4*)(A  + (size_t)(mBase + gr + i*32)*lda + (k4<<2));
        float4 vb = *(const float4*)(Bm + (size_t)(nBase + gr + i*32)*ldb + (k4<<2));
        stA[i] = make_uint4(f2tf(va.x), f2tf(va.y), f2tf(va.z), f2tf(va.w));
        stB[i] = make_uint4(f2tf(vb.x), f2tf(vb.y), f2tf(vb.z), f2tf(vb.w));
    }
    {
        uint4* dA = (uint4*)sA; uint4* dB = (uint4*)sB;
        #pragma unroll
        for (int i=0; i<4; ++i){
            dA[(gr + i*32)*8 + sw] = stA[i];
            dB[(gr + i*32)*8 + sw] = stB[i];
        }
    }
    __syncthreads();

    for (int kt=0; kt<KT; ++kt){
        if (kt+1 < KT){
            const int k0 = (kt+1) << 5;
            #pragma unroll
            for (int i=0; i<4; ++i){
                float4 va = *(const float4*)(A  + (size_t)(mBase + gr + i*32)*lda + k0 + (k4<<2));
                float4 vb = *(const float4*)(Bm + (size_t)(nBase + gr + i*32)*ldb + k0 + (k4<<2));
                stA[i] = make_uint4(f2tf(va.x), f2tf(va.y), f2tf(va.z), f2tf(va.w));
                stB[i] = make_uint4(f2tf(vb.x), f2tf(vb.y), f2tf(vb.z), f2tf(vb.w));
            }
        }
        const unsigned* cA = sA + (kt&1)*4096;
        const unsigned* cB = sB + (kt&1)*4096;
        #pragma unroll
        for (int ks=0; ks<4; ++ks){
            const int kk4 = ks*2;
            unsigned a[2][4], b[8][2];
            #pragma unroll
            for (int mt=0; mt<2; ++mt){
                const int r0 = wr*32 + mt*16 + lr, r1 = r0 + 8;
                const int s0 = r0 & 7, s1 = r1 & 7;
                a[mt][0] = cA[r0*32 + (( kk4    ^ s0)<<2) + lk];
                a[mt][1] = cA[r1*32 + (( kk4    ^ s1)<<2) + lk];
                a[mt][2] = cA[r0*32 + (((kk4+1) ^ s0)<<2) + lk];
                a[mt][3] = cA[r1*32 + (((kk4+1) ^ s1)<<2) + lk];
            }
            #pragma unroll
            for (int nt=0; nt<8; ++nt){
                const int rn = wc*64 + nt*8 + lr;
                const int sn = rn & 7;
                b[nt][0] = cB[rn*32 + (( kk4    ^ sn)<<2) + lk];
                b[nt][1] = cB[rn*32 + (((kk4+1) ^ sn)<<2) + lk];
            }
            #pragma unroll
            for (int mt=0; mt<2; ++mt)
                #pragma unroll
                for (int nt=0; nt<8; ++nt)
                    mma8(acc[mt][nt], a[mt], b[nt]);
        }
        if (kt+1 < KT){
            uint4* dA = (uint4*)(sA + ((kt+1)&1)*4096);
            uint4* dB = (uint4*)(sB + ((kt+1)&1)*4096);
            #pragma unroll
            for (int i=0; i<4; ++i){
                dA[(gr + i*32)*8 + sw] = stA[i];
                dB[(gr + i*32)*8 + sw] = stB[i];
            }
            __syncthreads();
        }
    }

    // epilogue
    #pragma unroll
    for (int mt=0; mt<2; ++mt)
      #pragma unroll
      for (int nt=0; nt<8; ++nt)
        #pragma unroll
        for (int i=0; i<4; ++i){
            const int m = mBase + wr*32 + mt*16 + lr + ((i>>1)<<3);
            const int n = nBase + wc*64 + nt*8 + (lk<<1) + (i&1);
            float v = acc[mt][nt][i];
            if (MODE == 0){
                v += bias[n];
                const int bb = m >> 11, t = m & 2047;
                if (n < 2048){
                    const int h = n >> 7, d = n & 127;
                    O0[((size_t)((bb*16+h)*2048 + t))*128 + d] = v;           // Q scratch
                } else if (n < 4096){
                    const int o = n - 2048, h = o >> 7, d = o & 127;
                    O1[((size_t)((bb*16+h)*2048 + t))*128 + d] = v;           // K out
                } else {
                    const int o = n - 4096, h = o >> 7, d = o & 127;
                    O2[((size_t)((bb*16+h)*2048 + t))*128 + d] = v;           // V out
                    O3[((size_t)((bb*16+h)*128  + d))*2048 + t] = v;          // V^T scratch
                }
            } else if (MODE == 1){
                O0[(size_t)bz*SEQ*SEQ + (size_t)m*SEQ + n] = v * 0.088388347648318447f;
            } else if (MODE == 2){
                const int bb = bz >> 4, h = bz & 15;
                O0[((size_t)(bb*SEQ + m))*CDIM + h*DK + n] = v;               // Y [b,t,c]
            } else {
                v += bias[n];
                O0[(size_t)m*CDIM + n] = v;
            }
        }
}

// Causal row softmax in place: P[q,j] = softmax_{j<=q}(S[q,j]), P[q,j>q]=0.
__global__ void __launch_bounds__(256)
softmax_causal(float* __restrict__ S)
{
    const int r  = blockIdx.x;
    const int bh = r >> 11, q = r & 2047;
    float* row = S + (size_t)bh*SEQ*SEQ + (size_t)q*SEQ;
    __shared__ float buf[SEQ];
    __shared__ float red[8];
    __shared__ float bc;
    const int tid = threadIdx.x;
    const int len = q + 1;

    float mx = -1e30f;
    for (int j = tid; j < len; j += 256){ float v = row[j]; buf[j] = v; mx = fmaxf(mx, v); }
    #pragma unroll
    for (int o=16; o; o>>=1) mx = fmaxf(mx, __shfl_xor_sync(0xffffffffu, mx, o));
    if ((tid & 31) == 0) red[tid>>5] = mx;
    __syncthreads();
    if (tid == 0){ float m = red[0]; for (int i=1;i<8;++i) m = fmaxf(m, red[i]); bc = m; }
    __syncthreads();
    mx = bc;

    float s = 0.f;
    for (int j = tid; j < len; j += 256){ float e = __expf(buf[j] - mx); buf[j] = e; s += e; }
    #pragma unroll
    for (int o=16; o; o>>=1) s += __shfl_xor_sync(0xffffffffu, s, o);
    if ((tid & 31) == 0) red[tid>>5] = s;
    __syncthreads();
    if (tid == 0){ float t = 0.f; for (int i=0;i<8;++i) t += red[i]; bc = t; }
    __syncthreads();

    const float inv = 1.f / bc;
    for (int j = tid; j < SEQ; j += 256) row[j] = (j < len) ? buf[j]*inv : 0.f;
}

extern "C" void kernel_launch(void* const* d_in, const int* in_sizes, int n_in,
                              void* d_out, int out_size)
{
    const float* x      = (const float*)d_in[0];
    const float* w_attn = (const float*)d_in[1];
    const float* b_attn = (const float*)d_in[2];
    const float* w_proj = (const float*)d_in[3];
    const float* b_proj = (const float*)d_in[4];

    float* yOut = (float*)d_out;
    float* kOut = yOut + (size_t)BTC;
    float* vOut = yOut + (size_t)2*BTC;

    float *Q, *VT, *S, *Y;
    cudaGetSymbolAddress((void**)&Q,  g_Q);
    cudaGetSymbolAddress((void**)&VT, g_VT);
    cudaGetSymbolAddress((void**)&S,  g_S);
    cudaGetSymbolAddress((void**)&Y,  g_Y);

    const int smem = 65536;
    cudaFuncSetAttribute(gemm_tf32<0>, cudaFuncAttributeMaxDynamicSharedMemorySize, smem);
    cudaFuncSetAttribute(gemm_tf32<1>, cudaFuncAttributeMaxDynamicSharedMemorySize, smem);
    cudaFuncSetAttribute(gemm_tf32<2>, cudaFuncAttributeMaxDynamicSharedMemorySize, smem);
    cudaFuncSetAttribute(gemm_tf32<3>, cudaFuncAttributeMaxDynamicSharedMemorySize, smem);

    // 1) QKV = x @ w_attn^T + b_attn   (M=8192, N=6144, K=2048)
    gemm_tf32<0><<<dim3(48,64,1), 256, smem>>>(x, w_attn, b_attn,
                                               Q, kOut, vOut, VT,
                                               8192, 6144, 2048, 2048, 2048);
    // 2) S = Q K^T / sqrt(dk), per head  (M=N=2048, K=128), causal tiles only
    gemm_tf32<1><<<dim3(16,16,64), 256, smem>>>(Q, kOut, nullptr,
                                                S, nullptr, nullptr, nullptr,
                                                2048, 2048, 128, 128, 128);
    // 3) causal softmax rows
    softmax_causal<<<BH*SEQ, 256>>>(S);
    // 4) Y = P V  (per head, K clipped causally inside), write [b,t,c]
    gemm_tf32<2><<<dim3(1,16,64), 256, smem>>>(S, VT, nullptr,
                                               Y, nullptr, nullptr, nullptr,
                                               2048, 128, 128, 2048, 2048);
    // 5) y = Y @ w_proj^T + b_proj
    gemm_tf32<3><<<dim3(16,64,1), 256, smem>>>(Y, w_proj, b_proj,
                                               yOut, nullptr, nullptr, nullptr,
                                               8192, 2048, 2048, 2048, 2048);
}

// round 2
// speedup vs baseline: 1.2536x; 1.2536x over previous
#include <cuda_runtime.h>
#include <cstdint>

#define BATCH 4
#define SEQ   2048
#define CDIM  2048
#define NH    16
#define DK    128
#define BH    (BATCH*NH)          /* 64  */
#define BTC   (BATCH*SEQ*CDIM)    /* 16777216 */

// Scratch (static device arrays: sanctioned scratch mechanism, no allocs)
__device__ float g_Q [(size_t)BH*SEQ*DK];     // Q in [b,h,t,d]   (64 MB)
__device__ float g_Y [(size_t)BATCH*SEQ*CDIM];// attn out [b,t,c] (64 MB)

__device__ __forceinline__ unsigned f2tf(float f){
    unsigned u; asm("cvt.rna.tf32.f32 %0, %1;" : "=r"(u) : "f"(f)); return u;
}
__device__ __forceinline__ unsigned packh2(float lo, float hi){
    unsigned d; asm("cvt.rn.f16x2.f32 %0, %1, %2;" : "=r"(d) : "f"(hi), "f"(lo)); return d;
}
__device__ __forceinline__ float ex2f(float x){
    float y; asm("ex2.approx.f32 %0, %1;" : "=f"(y) : "f"(x)); return y;
}
__device__ __forceinline__ void mma8(float* c, const unsigned* a, const unsigned* b){
    asm volatile("mma.sync.aligned.m16n8k8.row.col.f32.tf32.tf32.f32 "
        "{%0,%1,%2,%3}, {%4,%5,%6,%7}, {%8,%9}, {%0,%1,%2,%3};\n"
        : "+f"(c[0]), "+f"(c[1]), "+f"(c[2]), "+f"(c[3])
        : "r"(a[0]), "r"(a[1]), "r"(a[2]), "r"(a[3]), "r"(b[0]), "r"(b[1]));
}
__device__ __forceinline__ void mma16(float* c, unsigned a0, unsigned a1, unsigned a2,
                                      unsigned a3, unsigned b0, unsigned b1){
    asm volatile("mma.sync.aligned.m16n8k16.row.col.f32.f16.f16.f32 "
        "{%0,%1,%2,%3}, {%4,%5,%6,%7}, {%8,%9}, {%0,%1,%2,%3};\n"
        : "+f"(c[0]), "+f"(c[1]), "+f"(c[2]), "+f"(c[3])
        : "r"(a0), "r"(a1), "r"(a2), "r"(a3), "r"(b0), "r"(b1));
}
__device__ __forceinline__ void cpa(unsigned dst, const float* src){
    asm volatile("cp.async.cg.shared.global [%0], [%1], 16;\n" :: "r"(dst), "l"(src));
}
__device__ __forceinline__ void cpcommit(){ asm volatile("cp.async.commit_group;\n"); }
template<int N> __device__ __forceinline__ void cpwait(){
    asm volatile("cp.async.wait_group %0;\n" :: "n"(N));
}
// word index into a [128 rows][128 words] tile, xor-swizzled at float4 granularity
__device__ __forceinline__ int swi(int r, int c){
    int f = c >> 2;
    return r*128 + (((f & 24) | ((f & 7) ^ (r & 7))) << 2) + (c & 3);
}

// ===================== GEMM (QKV / proj), tf32 MMA =====================
// MODE 0: QKV   (A=x, B=w_attn)  epilogue: +bias, scatter Q/K/V
// MODE 3: proj  epilogue: +bias -> y out
template<int MODE>
__global__ void __launch_bounds__(256, 1)
gemm_tf32(const float* __restrict__ Ag, const float* __restrict__ Bg,
          const float* __restrict__ bias,
          float* __restrict__ O0, float* __restrict__ O1, float* __restrict__ O2,
          int M, int N, int K, int lda, int ldb)
{
    const int bx = blockIdx.x, by = blockIdx.y;
    const float* A  = Ag;
    const float* Bm = Bg;

    extern __shared__ unsigned smbuf[];
    unsigned* sA = smbuf;          // [2][128][32] tf32 words
    unsigned* sB = smbuf + 8192;   // [2][128][32]

    const int tid  = threadIdx.x;
    const int lane = tid & 31, warp = tid >> 5;
    const int wr = warp >> 1, wc = warp & 1;
    const int lr = lane >> 2, lk = lane & 3;
    const int mBase = by*128, nBase = bx*128;
    const int gr = tid >> 3, k4 = tid & 7;
    const int sw = k4 ^ (gr & 7);

    float acc[2][8][4];
    #pragma unroll
    for (int mt=0; mt<2; ++mt)
      #pragma unroll
      for (int nt=0; nt<8; ++nt)
        #pragma unroll
        for (int i=0; i<4; ++i) acc[mt][nt][i] = 0.f;

    uint4 stA[4], stB[4];
    const int KT = K >> 5;

    #pragma unroll
    for (int i=0; i<4; ++i){
        float4 va = *(const float4*)(A  + (size_t)(mBase + gr + i*32)*lda + (k4<<2));
        float4 vb = *(const float4*)(Bm + (size_t)(nBase + gr + i*32)*ldb + (k4<<2));
        stA[i] = make_uint4(f2tf(va.x), f2tf(va.y), f2tf(va.z), f2tf(va.w));
        stB[i] = make_uint4(f2tf(vb.x), f2tf(vb.y), f2tf(vb.z), f2tf(vb.w));
    }
    {
        uint4* dA = (uint4*)sA; uint4* dB = (uint4*)sB;
        #pragma unroll
        for (int i=0; i<4; ++i){
            dA[(gr + i*32)*8 + sw] = stA[i];
            dB[(gr + i*32)*8 + sw] = stB[i];
        }
    }
    __syncthreads();

    for (int kt=0; kt<KT; ++kt){
        if (kt+1 < KT){
            const int k0 = (kt+1) << 5;
            #pragma unroll
            for (int i=0; i<4; ++i){
                float4 va = *(const float4*)(A  + (size_t)(mBase + gr + i*32)*lda + k0 + (k4<<2));
                float4 vb = *(const float4*)(Bm + (size_t)(nBase + gr + i*32)*ldb + k0 + (k4<<2));
                stA[i] = make_uint4(f2tf(va.x), f2tf(va.y), f2tf(va.z), f2tf(va.w));
                stB[i] = make_uint4(f2tf(vb.x), f2tf(vb.y), f2tf(vb.z), f2tf(vb.w));
            }
        }
        const unsigned* cA = sA + (kt&1)*4096;
        const unsigned* cB = sB + (kt&1)*4096;
        #pragma unroll
        for (int ks=0; ks<4; ++ks){
            const int kk4 = ks*2;
            unsigned a[2][4], b[8][2];
            #pragma unroll
            for (int mt=0; mt<2; ++mt){
                const int r0 = wr*32 + mt*16 + lr, r1 = r0 + 8;
                const int s0 = r0 & 7, s1 = r1 & 7;
                a[mt][0] = cA[r0*32 + (( kk4    ^ s0)<<2) + lk];
                a[mt][1] = cA[r1*32 + (( kk4    ^ s1)<<2) + lk];
                a[mt][2] = cA[r0*32 + (((kk4+1) ^ s0)<<2) + lk];
                a[mt][3] = cA[r1*32 + (((kk4+1) ^ s1)<<2) + lk];
            }
            #pragma unroll
            for (int nt=0; nt<8; ++nt){
                const int rn = wc*64 + nt*8 + lr;
                const int sn = rn & 7;
                b[nt][0] = cB[rn*32 + (( kk4    ^ sn)<<2) + lk];
                b[nt][1] = cB[rn*32 + (((kk4+1) ^ sn)<<2) + lk];
            }
            #pragma unroll
            for (int mt=0; mt<2; ++mt)
                #pragma unroll
                for (int nt=0; nt<8; ++nt)
                    mma8(acc[mt][nt], a[mt], b[nt]);
        }
        if (kt+1 < KT){
            uint4* dA = (uint4*)(sA + ((kt+1)&1)*4096);
            uint4* dB = (uint4*)(sB + ((kt+1)&1)*4096);
            #pragma unroll
            for (int i=0; i<4; ++i){
                dA[(gr + i*32)*8 + sw] = stA[i];
                dB[(gr + i*32)*8 + sw] = stB[i];
            }
            __syncthreads();
        }
    }

    #pragma unroll
    for (int mt=0; mt<2; ++mt)
      #pragma unroll
      for (int nt=0; nt<8; ++nt)
        #pragma unroll
        for (int i=0; i<4; ++i){
            const int m = mBase + wr*32 + mt*16 + lr + ((i>>1)<<3);
            const int n = nBase + wc*64 + nt*8 + (lk<<1) + (i&1);
            float v = acc[mt][nt][i] + bias[n];
            if (MODE == 0){
                const int bb = m >> 11, t = m & 2047;
                if (n < 2048){
                    const int h = n >> 7, d = n & 127;
                    O0[((size_t)((bb*16+h)*2048 + t))*128 + d] = v;           // Q scratch
                } else if (n < 4096){
                    const int o = n - 2048, h = o >> 7, d = o & 127;
                    O1[((size_t)((bb*16+h)*2048 + t))*128 + d] = v;           // K out
                } else {
                    const int o = n - 4096, h = o >> 7, d = o & 127;
                    O2[((size_t)((bb*16+h)*2048 + t))*128 + d] = v;           // V out
                }
            } else {
                O0[(size_t)m*CDIM + n] = v;
            }
        }
}

// ===================== Fused flash attention =====================
// CTA = (q-tile of 128 rows, bh). 8 warps, warp w owns q rows [16w,16w+16).
// smem: sQ 64KB (tf32 swizzled), sK 64KB (tf32 after in-place cvt), sV 64KB fp32.
__global__ void __launch_bounds__(256, 1)
flash_attn(const float* __restrict__ Qg_, const float* __restrict__ Kg_,
           const float* __restrict__ Vg_, float* __restrict__ Yg)
{
    const int qtile = 15 - blockIdx.x;   // long blocks first
    const int bh    = blockIdx.y;
    const int tid   = threadIdx.x;
    const int lane  = tid & 31, w = tid >> 5;
    const int lr    = lane >> 2, lk = lane & 3;
    const int wrow  = w * 16;

    extern __shared__ unsigned sm[];
    unsigned* sQ = sm;
    unsigned* sK = sm + 16384;
    float*    sV = (float*)(sm + 32768);
    const unsigned sb  = (unsigned)__cvta_generic_to_shared(sm);
    const unsigned sKb = sb + 65536;
    const unsigned sVb = sb + 131072;

    const float* Qg = Qg_ + (size_t)bh*SEQ*DK + (size_t)qtile*16384;
    const float* Kg = Kg_ + (size_t)bh*SEQ*DK;
    const float* Vg = Vg_ + (size_t)bh*SEQ*DK;

    // prologue: issue K(0), V(0), load+convert Q
    #pragma unroll
    for (int i=0;i<16;++i){
        int idx = tid + i*256, r = idx>>5, f = idx&31;
        int fs = (f&24)|((f&7)^(r&7));
        cpa(sKb + (unsigned)(r*128+fs*4)*4u, Kg + r*128 + f*4);
    }
    cpcommit();
    #pragma unroll
    for (int i=0;i<16;++i){
        int idx = tid + i*256, r = idx>>5, f = idx&31;
        int fs = (f&24)|((f&7)^(r&7));
        cpa(sVb + (unsigned)(r*128+fs*4)*4u, Vg + r*128 + f*4);
    }
    cpcommit();
    const float qscale = (float)(1.4426950408889634 / 11.313708498984761); // log2e/sqrt(dk)
    #pragma unroll
    for (int i=0;i<16;++i){
        int idx = tid + i*256, r = idx>>5, f = idx&31;
        int fs = (f&24)|((f&7)^(r&7));
        float4 v = *(const float4*)(Qg + r*128 + f*4);
        uint4 u = make_uint4(f2tf(v.x*qscale), f2tf(v.y*qscale),
                             f2tf(v.z*qscale), f2tf(v.w*qscale));
        *(uint4*)(sQ + r*128 + fs*4) = u;
    }

    float m0=-1e30f, m1=-1e30f, l0=0.f, l1=0.f;
    float O[16][4];
    #pragma unroll
    for (int nt=0; nt<16; ++nt){ O[nt][0]=0.f; O[nt][1]=0.f; O[nt][2]=0.f; O[nt][3]=0.f; }

    for (int j = 0; j <= qtile; ++j){
        if (j == 0) cpwait<1>(); else cpwait<0>();
        __syncthreads();                       // K(j) visible; PV(j-1) done by all

        if (j > 0){                            // prefetch V(j): overlaps cvt + S
            const float* Vj = Vg + (size_t)j*16384;
            #pragma unroll
            for (int i=0;i<16;++i){
                int idx = tid + i*256, r = idx>>5, f = idx&31;
                int fs = (f&24)|((f&7)^(r&7));
                cpa(sVb + (unsigned)(r*128+fs*4)*4u, Vj + r*128 + f*4);
            }
            cpcommit();
        }

        // convert K(j) fp32 -> tf32 (rna) in place
        #pragma unroll
        for (int i=0;i<16;++i){
            int idx = tid + i*256, r = idx>>5, f = idx&31;
            int fs = (f&24)|((f&7)^(r&7));
            uint4* p = (uint4*)(sK + r*128 + fs*4);
            uint4 u = *p;
            u.x = f2tf(__uint_as_float(u.x)); u.y = f2tf(__uint_as_float(u.y));
            u.z = f2tf(__uint_as_float(u.z)); u.w = f2tf(__uint_as_float(u.w));
            *p = u;
        }
        __syncthreads();

        // S = Q K^T   (warp: 16 q-rows x 128 kv)
        float S[16][4];
        #pragma unroll
        for (int nt=0; nt<16; ++nt){ S[nt][0]=0.f; S[nt][1]=0.f; S[nt][2]=0.f; S[nt][3]=0.f; }
        #pragma unroll
        for (int ks=0; ks<16; ++ks){
            unsigned a[4];
            a[0] = sQ[swi(wrow+lr,   8*ks+lk)];
            a[1] = sQ[swi(wrow+lr+8, 8*ks+lk)];
            a[2] = sQ[swi(wrow+lr,   8*ks+4+lk)];
            a[3] = sQ[swi(wrow+lr+8, 8*ks+4+lk)];
            #pragma unroll
            for (int nt=0; nt<16; ++nt){
                unsigned b[2];
                b[0] = sK[swi(nt*8+lr, 8*ks+lk)];
                b[1] = sK[swi(nt*8+lr, 8*ks+4+lk)];
                mma8(S[nt], a, b);
            }
        }
        __syncthreads();                       // all warps done reading sK

        if (j < qtile){                        // prefetch K(j+1): overlaps PV
            const float* Kj = Kg + (size_t)(j+1)*16384;
            #pragma unroll
            for (int i=0;i<16;++i){
                int idx = tid + i*256, r = idx>>5, f = idx&31;
                int fs = (f&24)|((f&7)^(r&7));
                cpa(sKb + (unsigned)(r*128+fs*4)*4u, Kj + r*128 + f*4);
            }
            cpcommit();
            cpwait<1>();                       // V(j) done
        } else {
            cpwait<0>();
        }
        __syncthreads();                       // sV visible

        // causal mask on diagonal tile
        if (j == qtile){
            #pragma unroll
            for (int nt=0; nt<16; ++nt){
                const int c0 = nt*8 + 2*lk, c1 = c0 + 1;
                const int r0 = wrow + lr,   r1 = r0 + 8;
                if (c0 > r0) S[nt][0] = -1e30f;
                if (c1 > r0) S[nt][1] = -1e30f;
                if (c0 > r1) S[nt][2] = -1e30f;
                if (c1 > r1) S[nt][3] = -1e30f;
            }
        }

        // online softmax (base-2 domain; quad-local reductions)
        float mx0 = -1e30f, mx1 = -1e30f;
        #pragma unroll
        for (int nt=0; nt<16; ++nt){
            mx0 = fmaxf(mx0, fmaxf(S[nt][0], S[nt][1]));
            mx1 = fmaxf(mx1, fmaxf(S[nt][2], S[nt][3]));
        }
        mx0 = fmaxf(mx0, __shfl_xor_sync(0xffffffffu, mx0, 1));
        mx0 = fmaxf(mx0, __shfl_xor_sync(0xffffffffu, mx0, 2));
        mx1 = fmaxf(mx1, __shfl_xor_sync(0xffffffffu, mx1, 1));
        mx1 = fmaxf(mx1, __shfl_xor_sync(0xffffffffu, mx1, 2));
        const float nm0 = fmaxf(m0, mx0), nm1 = fmaxf(m1, mx1);
        const float f0 = ex2f(m0 - nm0), f1 = ex2f(m1 - nm1);
        float s0 = 0.f, s1 = 0.f;
        #pragma unroll
        for (int nt=0; nt<16; ++nt){
            S[nt][0] = ex2f(S[nt][0] - nm0); s0 += S[nt][0];
            S[nt][1] = ex2f(S[nt][1] - nm0); s0 += S[nt][1];
            S[nt][2] = ex2f(S[nt][2] - nm1); s1 += S[nt][2];
            S[nt][3] = ex2f(S[nt][3] - nm1); s1 += S[nt][3];
        }
        s0 += __shfl_xor_sync(0xffffffffu, s0, 1);
        s0 += __shfl_xor_sync(0xffffffffu, s0, 2);
        s1 += __shfl_xor_sync(0xffffffffu, s1, 1);
        s1 += __shfl_xor_sync(0xffffffffu, s1, 2);
        l0 = l0*f0 + s0; l1 = l1*f1 + s1; m0 = nm0; m1 = nm1;
        #pragma unroll
        for (int nt=0; nt<16; ++nt){
            O[nt][0] *= f0; O[nt][1] *= f0; O[nt][2] *= f1; O[nt][3] *= f1;
        }

        // O += P @ V   (P from S regs via the accumulator->A-fragment identity)
        #pragma unroll
        for (int kk=0; kk<8; ++kk){
            const unsigned a0 = packh2(S[2*kk  ][0], S[2*kk  ][1]);
            const unsigned a1 = packh2(S[2*kk  ][2], S[2*kk  ][3]);
            const unsigned a2 = packh2(S[2*kk+1][0], S[2*kk+1][1]);
            const unsigned a3 = packh2(S[2*kk+1][2], S[2*kk+1][3]);
            #pragma unroll
            for (int nt=0; nt<16; ++nt){
                const float v00 = sV[swi(16*kk+2*lk,   nt*8+lr)];
                const float v01 = sV[swi(16*kk+2*lk+1, nt*8+lr)];
                const float v10 = sV[swi(16*kk+2*lk+8, nt*8+lr)];
                const float v11 = sV[swi(16*kk+2*lk+9, nt*8+lr)];
                mma16(O[nt], a0, a1, a2, a3, packh2(v00, v01), packh2(v10, v11));
            }
        }
    }

    // epilogue: normalize and write Y[b, t, h*128 + d]
    const float inv0 = 1.f / l0, inv1 = 1.f / l1;
    const int rg = qtile*128 + wrow + lr;
    const size_t base = ((size_t)(bh>>4)*SEQ + rg)*CDIM + (bh&15)*DK;
    #pragma unroll
    for (int nt=0; nt<16; ++nt){
        float2 t0 = make_float2(O[nt][0]*inv0, O[nt][1]*inv0);
        float2 t1 = make_float2(O[nt][2]*inv1, O[nt][3]*inv1);
        *(float2*)(Yg + base + nt*8 + 2*lk)            = t0;
        *(float2*)(Yg + base + (size_t)8*CDIM + nt*8 + 2*lk) = t1;
    }
}

extern "C" void kernel_launch(void* const* d_in, const int* in_sizes, int n_in,
                              void* d_out, int out_size)
{
    const float* x      = (const float*)d_in[0];
    const float* w_attn = (const float*)d_in[1];
    const float* b_attn = (const float*)d_in[2];
    const float* w_proj = (const float*)d_in[3];
    const float* b_proj = (const float*)d_in[4];

    float* yOut = (float*)d_out;
    float* kOut = yOut + (size_t)BTC;
    float* vOut = yOut + (size_t)2*BTC;

    float *Q, *Y;
    cudaGetSymbolAddress((void**)&Q, g_Q);
    cudaGetSymbolAddress((void**)&Y, g_Y);

    const int smemG = 65536;
    const int smemF = 196608;
    cudaFuncSetAttribute(gemm_tf32<0>, cudaFuncAttributeMaxDynamicSharedMemorySize, smemG);
    cudaFuncSetAttribute(gemm_tf32<3>, cudaFuncAttributeMaxDynamicSharedMemorySize, smemG);
    cudaFuncSetAttribute(flash_attn,   cudaFuncAttributeMaxDynamicSharedMemorySize, smemF);

    // 1) QKV = x @ w_attn^T + b_attn   (M=8192, N=6144, K=2048)
    gemm_tf32<0><<<dim3(48,64,1), 256, smemG>>>(x, w_attn, b_attn,
                                                Q, kOut, vOut,
                                                8192, 6144, 2048, 2048, 2048);
    // 2) fused flash attention: Y = softmax(QK^T/sqrt(dk), causal) V
    flash_attn<<<dim3(16,64,1), 256, smemF>>>(Q, kOut, vOut, Y);
    // 3) y = Y @ w_proj^T + b_proj
    gemm_tf32<3><<<dim3(16,64,1), 256, smemG>>>(Y, w_proj, b_proj,
                                                yOut, nullptr, nullptr,
                                                8192, 2048, 2048, 2048, 2048);
}

// round 4
// speedup vs baseline: 1.4720x; 1.1742x over previous
#include <cuda_runtime.h>
#include <cuda_fp16.h>
#include <cstdint>

#define BATCH 4
#define SEQ   2048
#define CDIM  2048
#define NH    16
#define DK    128
#define BH    (BATCH*NH)          /* 64  */
#define BTC   (BATCH*SEQ*CDIM)    /* 16777216 */

// Scratch (static device arrays: sanctioned scratch mechanism, no allocs)
__device__ float g_Q [(size_t)BH*SEQ*DK];      // Q in [b,h,t,d]   (64 MB)
__device__ float g_Y [(size_t)BATCH*SEQ*CDIM]; // attn out [b,t,c] (64 MB)

__device__ __forceinline__ unsigned packh2(float lo, float hi){
    unsigned d; asm("cvt.rn.f16x2.f32 %0, %1, %2;" : "=r"(d) : "f"(hi), "f"(lo)); return d;
}
__device__ __forceinline__ float ex2f(float x){
    float y; asm("ex2.approx.f32 %0, %1;" : "=f"(y) : "f"(x)); return y;
}
__device__ __forceinline__ void mma16(float* c, unsigned a0, unsigned a1, unsigned a2,
                                      unsigned a3, unsigned b0, unsigned b1){
    asm volatile("mma.sync.aligned.m16n8k16.row.col.f32.f16.f16.f32 "
        "{%0,%1,%2,%3}, {%4,%5,%6,%7}, {%8,%9}, {%0,%1,%2,%3};\n"
        : "+f"(c[0]), "+f"(c[1]), "+f"(c[2]), "+f"(c[3])
        : "r"(a0), "r"(a1), "r"(a2), "r"(a3), "r"(b0), "r"(b1));
}
__device__ __forceinline__ void cpa(unsigned dst, const float* src){
    asm volatile("cp.async.cg.shared.global [%0], [%1], 16;\n" :: "r"(dst), "l"(src));
}
__device__ __forceinline__ void cpcommit(){ asm volatile("cp.async.commit_group;\n"); }
template<int N> __device__ __forceinline__ void cpwait(){
    asm volatile("cp.async.wait_group %0;\n" :: "n"(N));
}
// word index into a [128 rows][128 words] fp32 tile (512B rows), 16B-granularity xor swizzle
__device__ __forceinline__ int swi(int r, int c){
    int f = c >> 2;
    return r*128 + (((f & 24) | ((f & 7) ^ (r & 7))) << 2) + (c & 3);
}
// half index into a [128 rows][128 halfs] fp16 tile (256B rows), 16B-granularity xor swizzle
__device__ __forceinline__ int swh(int r, int h){
    int g = h >> 3;
    return r*128 + (((g & 8) | ((g & 7) ^ (r & 7))) << 3) + (h & 7);
}
// half index into a [128 rows][32 halfs] fp16 tile (64B rows), 8B-granularity xor swizzle
__device__ __forceinline__ int swg(int r, int h){
    return r*32 + ((((h >> 2) ^ (r & 7))) << 2) + (h & 3);
}

// ===================== fp16 MMA GEMM (QKV / proj) =====================
// D[128,128] CTA tile = A[128rows,K=2048] @ B[128rows,K=2048]^T, fp32 accum, +bias.
// MODE 0: QKV (scatter to Q scratch / K out / V out). MODE 1: proj (row-major out).
template<int MODE>
__global__ void __launch_bounds__(256, 1)
gemm_f16(const float* __restrict__ Ag, const float* __restrict__ Bg,
         const float* __restrict__ bias,
         float* __restrict__ O0, float* __restrict__ O1, float* __restrict__ O2)
{
    __shared__ __half sT[2][2][4096];   // [stage][A|B][128 rows x 32 halfs]

    const int tid  = threadIdx.x;
    const int lane = tid & 31, warp = tid >> 5;
    const int wr = warp >> 1, wc = warp & 1;      // warp grid 4x2 -> warp tile 32x64
    const int lr = lane >> 2, lk = lane & 3;
    const int bx = blockIdx.x, by = blockIdx.y;
    const int mBase = by*128, nBase = bx*128;

    const float* A = Ag + (size_t)mBase*2048;
    const float* B = Bg + (size_t)nBase*2048;

    const int r = tid >> 1, q = tid & 1;          // g2s: row r, halfs [16q,16q+16)

    float acc[2][8][4];
    #pragma unroll
    for (int mt=0; mt<2; ++mt)
      #pragma unroll
      for (int nt=0; nt<8; ++nt)
        #pragma unroll
        for (int i=0; i<4; ++i) acc[mt][nt][i] = 0.f;

    float4 stA[4], stB[4];

    // prologue: chunk 0
    {
        const float* a = A + (size_t)r*2048 + q*16;
        const float* b = B + (size_t)r*2048 + q*16;
        #pragma unroll
        for (int i=0;i<4;++i){ stA[i] = *(const float4*)(a + 4*i); stB[i] = *(const float4*)(b + 4*i); }
        #pragma unroll
        for (int i=0;i<4;++i){
            int gs = (q*4 + i) ^ (r & 7);
            *(uint2*)&sT[0][0][r*32 + gs*4] = make_uint2(packh2(stA[i].x,stA[i].y), packh2(stA[i].z,stA[i].w));
            *(uint2*)&sT[0][1][r*32 + gs*4] = make_uint2(packh2(stB[i].x,stB[i].y), packh2(stB[i].z,stB[i].w));
        }
    }
    __syncthreads();

    for (int kt=0; kt<64; ++kt){
        if (kt+1 < 64){
            const float* a = A + (size_t)r*2048 + (kt+1)*32 + q*16;
            const float* b = B + (size_t)r*2048 + (kt+1)*32 + q*16;
            #pragma unroll
            for (int i=0;i<4;++i){ stA[i] = *(const float4*)(a + 4*i); stB[i] = *(const float4*)(b + 4*i); }
        }
        const __half* cA = sT[kt&1][0];
        const __half* cB = sT[kt&1][1];
        #pragma unroll
        for (int ks=0; ks<2; ++ks){
            unsigned a[2][4], b[8][2];
            #pragma unroll
            for (int mt=0; mt<2; ++mt){
                const int r0 = wr*32 + mt*16 + lr, r1 = r0 + 8;
                a[mt][0] = *(const unsigned*)&cA[swg(r0, ks*16 + 2*lk)];
                a[mt][1] = *(const unsigned*)&cA[swg(r1, ks*16 + 2*lk)];
                a[mt][2] = *(const unsigned*)&cA[swg(r0, ks*16 + 8 + 2*lk)];
                a[mt][3] = *(const unsigned*)&cA[swg(r1, ks*16 + 8 + 2*lk)];
            }
            #pragma unroll
            for (int nt=0; nt<8; ++nt){
                const int rn = wc*64 + nt*8 + lr;
                b[nt][0] = *(const unsigned*)&cB[swg(rn, ks*16 + 2*lk)];
                b[nt][1] = *(const unsigned*)&cB[swg(rn, ks*16 + 8 + 2*lk)];
            }
            #pragma unroll
            for (int mt=0; mt<2; ++mt)
                #pragma unroll
                for (int nt=0; nt<8; ++nt)
                    mma16(acc[mt][nt], a[mt][0], a[mt][1], a[mt][2], a[mt][3], b[nt][0], b[nt][1]);
        }
        if (kt+1 < 64){
            const int st = (kt+1)&1;
            #pragma unroll
            for (int i=0;i<4;++i){
                int gs = (q*4 + i) ^ (r & 7);
                *(uint2*)&sT[st][0][r*32 + gs*4] = make_uint2(packh2(stA[i].x,stA[i].y), packh2(stA[i].z,stA[i].w));
                *(uint2*)&sT[st][1][r*32 + gs*4] = make_uint2(packh2(stB[i].x,stB[i].y), packh2(stB[i].z,stB[i].w));
            }
            __syncthreads();
        }
    }

    // epilogue
    #pragma unroll
    for (int mt=0; mt<2; ++mt)
      #pragma unroll
      for (int nt=0; nt<8; ++nt)
        #pragma unroll
        for (int i=0; i<4; ++i){
            const int m = mBase + wr*32 + mt*16 + lr + ((i>>1)<<3);
            const int n = nBase + wc*64 + nt*8 + (lk<<1) + (i&1);
            float v = acc[mt][nt][i] + bias[n];
            if (MODE == 0){
                const int bb = m >> 11, t = m & 2047;
                if (n < 2048){
                    const int h = n >> 7, d = n & 127;
                    O0[((size_t)((bb*16+h)*2048 + t))*128 + d] = v;           // Q scratch
                } else if (n < 4096){
                    const int o = n - 2048, h = o >> 7, d = o & 127;
                    O1[((size_t)((bb*16+h)*2048 + t))*128 + d] = v;           // K out
                } else {
                    const int o = n - 4096, h = o >> 7, d = o & 127;
                    O2[((size_t)((bb*16+h)*2048 + t))*128 + d] = v;           // V out
                }
            } else {
                O0[(size_t)m*CDIM + n] = v;
            }
        }
}

// ===================== Fused flash attention (fp16 MMA) =====================
// CTA = (q-tile of 128 rows, bh). 8 warps, warp w owns q rows [16w,16w+16).
// smem: sQh 32KB fp16 | sKh 32KB fp16 | sK32 64KB fp32 landing | sV 64KB fp32.
__global__ void __launch_bounds__(256, 1)
flash_attn(const float* __restrict__ Qg_, const float* __restrict__ Kg_,
           const float* __restrict__ Vg_, float* __restrict__ Yg)
{
    const int qtile = 15 - blockIdx.x;   // long blocks first
    const int bh    = blockIdx.y;
    const int tid   = threadIdx.x;
    const int lane  = tid & 31, w = tid >> 5;
    const int lr    = lane >> 2, lk = lane & 3;
    const int wrow  = w * 16;

    extern __shared__ unsigned sm[];
    __half*   sQh  = (__half*)sm;                      // 32KB
    __half*   sKh  = (__half*)((char*)sm + 32768);     // 32KB
    unsigned* sK32 = sm + 16384;                       // 64KB fp32 words (offset 65536B)
    float*    sV   = (float*)((char*)sm + 131072);     // 64KB
    const unsigned sb  = (unsigned)__cvta_generic_to_shared(sm);
    const unsigned sKb = sb + 65536;
    const unsigned sVb = sb + 131072;

    const float* Qg = Qg_ + (size_t)bh*SEQ*DK + (size_t)qtile*16384;
    const float* Kg = Kg_ + (size_t)bh*SEQ*DK;
    const float* Vg = Vg_ + (size_t)bh*SEQ*DK;

    // prologue: issue K32(0), V(0); stage Q -> fp16
    #pragma unroll
    for (int i=0;i<16;++i){
        int idx = tid + i*256, r = idx>>5, f = idx&31;
        int fs = (f&24)|((f&7)^(r&7));
        cpa(sKb + (unsigned)(r*128+fs*4)*4u, Kg + r*128 + f*4);
    }
    cpcommit();
    #pragma unroll
    for (int i=0;i<16;++i){
        int idx = tid + i*256, r = idx>>5, f = idx&31;
        int fs = (f&24)|((f&7)^(r&7));
        cpa(sVb + (unsigned)(r*128+fs*4)*4u, Vg + r*128 + f*4);
    }
    cpcommit();
    const float qscale = (float)(1.4426950408889634 / 11.313708498984761); // log2e/sqrt(dk)
    #pragma unroll
    for (int i=0;i<16;++i){
        int idx = tid + i*256, r = idx>>5, f = idx&31;
        float4 v = *(const float4*)(Qg + r*128 + f*4);
        *(uint2*)&sQh[swh(r, 4*f)] =
            make_uint2(packh2(v.x*qscale, v.y*qscale), packh2(v.z*qscale, v.w*qscale));
    }

    float m0=-1e30f, m1=-1e30f, l0=0.f, l1=0.f;
    float O[16][4];
    #pragma unroll
    for (int nt=0; nt<16; ++nt){ O[nt][0]=0.f; O[nt][1]=0.f; O[nt][2]=0.f; O[nt][3]=0.f; }

    for (int j = 0; j <= qtile; ++j){
        cpwait<1>();                       // K32(j) arrived (V(j) may be pending)
        __syncthreads();

        // convert K32(j) -> fp16 sKh
        #pragma unroll
        for (int i=0;i<16;++i){
            int idx = tid + i*256, r = idx>>5, f = idx&31;
            int fs = (f&24)|((f&7)^(r&7));
            uint4 u = *(uint4*)(sK32 + r*128 + fs*4);
            *(uint2*)&sKh[swh(r, 4*f)] =
                make_uint2(packh2(__uint_as_float(u.x), __uint_as_float(u.y)),
                           packh2(__uint_as_float(u.z), __uint_as_float(u.w)));
        }
        __syncthreads();

        if (j < qtile){                    // K32 free: prefetch K(j+1) now (overlaps S+PV)
            const float* Kj = Kg + (size_t)(j+1)*16384;
            #pragma unroll
            for (int i=0;i<16;++i){
                int idx = tid + i*256, r = idx>>5, f = idx&31;
                int fs = (f&24)|((f&7)^(r&7));
                cpa(sKb + (unsigned)(r*128+fs*4)*4u, Kj + r*128 + f*4);
            }
            cpcommit();
        }

        // S = Q K^T  (fp16 MMA, 8 k16 steps)
        float S[16][4];
        #pragma unroll
        for (int nt=0; nt<16; ++nt){ S[nt][0]=0.f; S[nt][1]=0.f; S[nt][2]=0.f; S[nt][3]=0.f; }
        #pragma unroll
        for (int ks=0; ks<8; ++ks){
            const int hk = ks*16 + 2*lk;
            const unsigned a0 = *(const unsigned*)&sQh[swh(wrow+lr,   hk)];
            const unsigned a1 = *(const unsigned*)&sQh[swh(wrow+lr+8, hk)];
            const unsigned a2 = *(const unsigned*)&sQh[swh(wrow+lr,   hk+8)];
            const unsigned a3 = *(const unsigned*)&sQh[swh(wrow+lr+8, hk+8)];
            #pragma unroll
            for (int nt=0; nt<16; ++nt){
                const unsigned b0 = *(const unsigned*)&sKh[swh(nt*8+lr, hk)];
                const unsigned b1 = *(const unsigned*)&sKh[swh(nt*8+lr, hk+8)];
                mma16(S[nt], a0, a1, a2, a3, b0, b1);
            }
        }

        if (j < qtile) cpwait<1>(); else cpwait<0>();   // V(j) done
        __syncthreads();                                // sV visible to all

        // causal mask on diagonal tile
        if (j == qtile){
            #pragma unroll
            for (int nt=0; nt<16; ++nt){
                const int c0 = nt*8 + 2*lk, c1 = c0 + 1;
                const int r0 = wrow + lr,   r1 = r0 + 8;
                if (c0 > r0) S[nt][0] = -1e30f;
                if (c1 > r0) S[nt][1] = -1e30f;
                if (c0 > r1) S[nt][2] = -1e30f;
                if (c1 > r1) S[nt][3] = -1e30f;
            }
        }

        // online softmax (base-2 domain; quad-local reductions)
        float mx0 = -1e30f, mx1 = -1e30f;
        #pragma unroll
        for (int nt=0; nt<16; ++nt){
            mx0 = fmaxf(mx0, fmaxf(S[nt][0], S[nt][1]));
            mx1 = fmaxf(mx1, fmaxf(S[nt][2], S[nt][3]));
        }
        mx0 = fmaxf(mx0, __shfl_xor_sync(0xffffffffu, mx0, 1));
        mx0 = fmaxf(mx0, __shfl_xor_sync(0xffffffffu, mx0, 2));
        mx1 = fmaxf(mx1, __shfl_xor_sync(0xffffffffu, mx1, 1));
        mx1 = fmaxf(mx1, __shfl_xor_sync(0xffffffffu, mx1, 2));
        const float nm0 = fmaxf(m0, mx0), nm1 = fmaxf(m1, mx1);
        const float f0 = ex2f(m0 - nm0), f1 = ex2f(m1 - nm1);
        float s0 = 0.f, s1 = 0.f;
        #pragma unroll
        for (int nt=0; nt<16; ++nt){
            S[nt][0] = ex2f(S[nt][0] - nm0); s0 += S[nt][0];
            S[nt][1] = ex2f(S[nt][1] - nm0); s0 += S[nt][1];
            S[nt][2] = ex2f(S[nt][2] - nm1); s1 += S[nt][2];
            S[nt][3] = ex2f(S[nt][3] - nm1); s1 += S[nt][3];
        }
        s0 += __shfl_xor_sync(0xffffffffu, s0, 1);
        s0 += __shfl_xor_sync(0xffffffffu, s0, 2);
        s1 += __shfl_xor_sync(0xffffffffu, s1, 1);
        s1 += __shfl_xor_sync(0xffffffffu, s1, 2);
        l0 = l0*f0 + s0; l1 = l1*f1 + s1; m0 = nm0; m1 = nm1;
        #pragma unroll
        for (int nt=0; nt<16; ++nt){
            O[nt][0] *= f0; O[nt][1] *= f0; O[nt][2] *= f1; O[nt][3] *= f1;
        }

        // O += P @ V   (P from S regs via the accumulator->A-fragment identity)
        #pragma unroll
        for (int kk=0; kk<8; ++kk){
            const unsigned a0 = packh2(S[2*kk  ][0], S[2*kk  ][1]);
            const unsigned a1 = packh2(S[2*kk  ][2], S[2*kk  ][3]);
            const unsigned a2 = packh2(S[2*kk+1][0], S[2*kk+1][1]);
            const unsigned a3 = packh2(S[2*kk+1][2], S[2*kk+1][3]);
            #pragma unroll
            for (int nt=0; nt<16; ++nt){
                const float v00 = sV[swi(16*kk+2*lk,   nt*8+lr)];
                const float v01 = sV[swi(16*kk+2*lk+1, nt*8+lr)];
                const float v10 = sV[swi(16*kk+2*lk+8, nt*8+lr)];
                const float v11 = sV[swi(16*kk+2*lk+9, nt*8+lr)];
                mma16(O[nt], a0, a1, a2, a3, packh2(v00, v01), packh2(v10, v11));
            }
        }

        __syncthreads();                                // all done reading sV
        if (j < qtile){                                 // prefetch V(j+1)
            const float* Vj = Vg + (size_t)(j+1)*16384;
            #pragma unroll
            for (int i=0;i<16;++i){
                int idx = tid + i*256, r = idx>>5, f = idx&31;
                int fs = (f&24)|((f&7)^(r&7));
                cpa(sVb + (unsigned)(r*128+fs*4)*4u, Vj + r*128 + f*4);
            }
            cpcommit();
        }
    }

    // epilogue: normalize and write Y[b, t, h*128 + d]
    const float inv0 = 1.f / l0, inv1 = 1.f / l1;
    const int rg = qtile*128 + wrow + lr;
    const size_t base = ((size_t)(bh>>4)*SEQ + rg)*CDIM + (bh&15)*DK;
    #pragma unroll
    for (int nt=0; nt<16; ++nt){
        float2 t0 = make_float2(O[nt][0]*inv0, O[nt][1]*inv0);
        float2 t1 = make_float2(O[nt][2]*inv1, O[nt][3]*inv1);
        *(float2*)(Yg + base + nt*8 + 2*lk)                  = t0;
        *(float2*)(Yg + base + (size_t)8*CDIM + nt*8 + 2*lk) = t1;
    }
}

extern "C" void kernel_launch(void* const* d_in, const int* in_sizes, int n_in,
                              void* d_out, int out_size)
{
    const float* x      = (const float*)d_in[0];
    const float* w_attn = (const float*)d_in[1];
    const float* b_attn = (const float*)d_in[2];
    const float* w_proj = (const float*)d_in[3];
    const float* b_proj = (const float*)d_in[4];

    float* yOut = (float*)d_out;
    float* kOut = yOut + (size_t)BTC;
    float* vOut = yOut + (size_t)2*BTC;

    float *Q, *Y;
    cudaGetSymbolAddress((void**)&Q, g_Q);
    cudaGetSymbolAddress((void**)&Y, g_Y);

    const int smemF = 196608;
    cudaFuncSetAttribute(flash_attn, cudaFuncAttributeMaxDynamicSharedMemorySize, smemF);

    // 1) QKV = x @ w_attn^T + b_attn   (M=8192, N=6144, K=2048), fp16 MMA
    gemm_f16<0><<<dim3(48,64), 256>>>(x, w_attn, b_attn, Q, kOut, vOut);

    // 2) fused flash attention: Y = softmax(QK^T/sqrt(dk), causal) V
    flash_attn<<<dim3(16,64), 256, smemF>>>(Q, kOut, vOut, Y);

    // 3) y = Y @ w_proj^T + b_proj   (M=8192, N=2048, K=2048), fp16 MMA
    gemm_f16<1><<<dim3(16,64), 256>>>(Y, w_proj, b_proj, yOut, nullptr, nullptr);
}

// round 5
// speedup vs baseline: 2.8413x; 1.9303x over previous
#include <cuda_runtime.h>
#include <cuda_fp16.h>
#include <cstdint>

#define BATCH 4
#define SEQ   2048
#define CDIM  2048
#define NH    16
#define DK    128
#define BH    (BATCH*NH)          /* 64  */
#define BTC   (BATCH*SEQ*CDIM)    /* 16777216 */

// Scratch (static device arrays: sanctioned scratch mechanism, no allocs)
__device__ float g_Q [(size_t)BH*SEQ*DK];                  // Q fp32 [b,h,t,d] (64 MB)
__device__ __align__(16) __half g_Xh [(size_t)BTC];        // x   fp16 (32 MB)
__device__ __align__(16) __half g_WAh[(size_t)3*CDIM*CDIM];// w_attn fp16 (24 MB)
__device__ __align__(16) __half g_WPh[(size_t)CDIM*CDIM];  // w_proj fp16 (8 MB)
__device__ __align__(16) __half g_Yh [(size_t)BTC];        // attn out fp16 [b,t,c] (32 MB)

__device__ __forceinline__ unsigned packh2(float lo, float hi){
    unsigned d; asm("cvt.rn.f16x2.f32 %0, %1, %2;" : "=r"(d) : "f"(hi), "f"(lo)); return d;
}
__device__ __forceinline__ float ex2f(float x){
    float y; asm("ex2.approx.f32 %0, %1;" : "=f"(y) : "f"(x)); return y;
}
__device__ __forceinline__ void mma16(float* c, unsigned a0, unsigned a1, unsigned a2,
                                      unsigned a3, unsigned b0, unsigned b1){
    asm volatile("mma.sync.aligned.m16n8k16.row.col.f32.f16.f16.f32 "
        "{%0,%1,%2,%3}, {%4,%5,%6,%7}, {%8,%9}, {%0,%1,%2,%3};\n"
        : "+f"(c[0]), "+f"(c[1]), "+f"(c[2]), "+f"(c[3])
        : "r"(a0), "r"(a1), "r"(a2), "r"(a3), "r"(b0), "r"(b1));
}
__device__ __forceinline__ void ldsm4(unsigned* r, unsigned addr){
    asm volatile("ldmatrix.sync.aligned.m8n8.x4.shared.b16 {%0,%1,%2,%3}, [%4];"
        : "=r"(r[0]), "=r"(r[1]), "=r"(r[2]), "=r"(r[3]) : "r"(addr));
}
__device__ __forceinline__ void cpa(unsigned dst, const void* src){
    asm volatile("cp.async.cg.shared.global [%0], [%1], 16;\n" :: "r"(dst), "l"(src));
}
__device__ __forceinline__ void cpcommit(){ asm volatile("cp.async.commit_group;\n"); }
template<int N> __device__ __forceinline__ void cpwait(){
    asm volatile("cp.async.wait_group %0;\n" :: "n"(N));
}
// word index into a [128 rows][128 words] fp32 tile (512B rows), 16B-granularity xor swizzle
__device__ __forceinline__ int swi(int r, int c){
    int f = c >> 2;
    return r*128 + (((f & 24) | ((f & 7) ^ (r & 7))) << 2) + (c & 3);
}
// half index into a [128 rows][128 halfs] fp16 tile (256B rows), 16B-granularity xor swizzle
__device__ __forceinline__ int swh(int r, int h){
    int g = h >> 3;
    return r*128 + (((g & 8) | ((g & 7) ^ (r & 7))) << 3) + (h & 7);
}

// ===================== fp32 -> fp16 conversion (8 elems/thread) =====================
__global__ void __launch_bounds__(256)
cvt_f16(const float* __restrict__ in, __half* __restrict__ out)
{
    const size_t i = ((size_t)blockIdx.x*256 + threadIdx.x)*8;
    float4 a = *(const float4*)(in + i);
    float4 b = *(const float4*)(in + i + 4);
    uint4 o = make_uint4(packh2(a.x,a.y), packh2(a.z,a.w), packh2(b.x,b.y), packh2(b.z,b.w));
    *(uint4*)(out + i) = o;
}

// ===================== fp16 GEMM: cp.async 4-stage + ldmatrix =====================
// D[128,256] CTA tile = A[128rows,K] @ B[256rows,K]^T, fp32 accum, +bias.
// 8 warps as 2(m) x 4(n); warp tile 64x64. K-chunk 64. K=2048.
// MODE 0: QKV (scatter Q fp32 scratch / K out / V out). MODE 1: proj (row-major out).
template<int MODE>
__global__ void __launch_bounds__(256, 1)
gemm_h(const __half* __restrict__ Ag, const __half* __restrict__ Bg,
       const float* __restrict__ bias,
       float* __restrict__ O0, float* __restrict__ O1, float* __restrict__ O2)
{
    extern __shared__ __half sh[];   // 4 stages x (A 128x64 | B 256x64) halfs = 192KB
    const unsigned sb = (unsigned)__cvta_generic_to_shared(sh);
    const int tid  = threadIdx.x;
    const int lane = tid & 31, w = tid >> 5;
    const int wm = w >> 2, wn = w & 3;
    const int lr = lane >> 2, lk = lane & 3;
    const int mBase = blockIdx.y*128, nBase = blockIdx.x*256;

    const __half* A = Ag + (size_t)mBase*2048;
    const __half* B = Bg + (size_t)nBase*2048;

    // ldmatrix lane address components
    const int l15 = lane & 15;
    int aRow[4], bRow[4];
    #pragma unroll
    for (int mt=0; mt<4; ++mt)  aRow[mt]  = wm*64 + mt*16 + l15;
    #pragma unroll
    for (int np=0; np<4; ++np)  bRow[np]  = wn*64 + np*16 + ((lane>>4)<<3) + (lane&7);
    const int gA = lane >> 4;            // k-group offset 0/1
    const int gB = (lane >> 3) & 1;

    float acc[4][8][4];
    #pragma unroll
    for (int mt=0; mt<4; ++mt)
      #pragma unroll
      for (int nt=0; nt<8; ++nt)
        #pragma unroll
        for (int i=0; i<4; ++i) acc[mt][nt][i] = 0.f;

    // cp.async stage fill: A 4 chunks/thread, B 8 chunks/thread (16B each)
    auto issue = [&](int slot, int kt){
        const unsigned st = sb + (unsigned)slot*49152u;
        #pragma unroll
        for (int i=0;i<4;++i){
            int idx = tid + i*256, r = idx>>3, g = idx&7;
            cpa(st + (unsigned)(r*128) + (unsigned)((g^(r&7))<<4),
                A + (size_t)r*2048 + kt*64 + g*8);
        }
        #pragma unroll
        for (int i=0;i<8;++i){
            int idx = tid + i*256, r = idx>>3, g = idx&7;
            cpa(st + 16384u + (unsigned)(r*128) + (unsigned)((g^(r&7))<<4),
                B + (size_t)r*2048 + kt*64 + g*8);
        }
    };

    issue(0,0); cpcommit();
    issue(1,1); cpcommit();
    issue(2,2); cpcommit();

    const int KT = 32;
    for (int kt=0; kt<KT; ++kt){
        cpwait<2>();
        __syncthreads();
        const unsigned stA = sb + (unsigned)(kt&3)*49152u;
        const unsigned stB = stA + 16384u;
        #pragma unroll
        for (int ks=0; ks<4; ++ks){
            unsigned af[4][4], bf[4][4];
            #pragma unroll
            for (int mt=0; mt<4; ++mt){
                const int r = aRow[mt];
                ldsm4(af[mt], stA + (unsigned)(r*128) + (unsigned)(((2*ks+gA)^(r&7))<<4));
            }
            #pragma unroll
            for (int np=0; np<4; ++np){
                const int r = bRow[np];
                ldsm4(bf[np], stB + (unsigned)(r*128) + (unsigned)(((2*ks+gB)^(r&7))<<4));
            }
            #pragma unroll
            for (int mt=0; mt<4; ++mt)
                #pragma unroll
                for (int nt=0; nt<8; ++nt)
                    mma16(acc[mt][nt], af[mt][0], af[mt][1], af[mt][2], af[mt][3],
                          bf[nt>>1][2*(nt&1)], bf[nt>>1][2*(nt&1)+1]);
        }
        if (kt+3 < KT) issue((kt+3)&3, kt+3);
        cpcommit();
    }

    // epilogue
    #pragma unroll
    for (int mt=0; mt<4; ++mt)
      #pragma unroll
      for (int nt=0; nt<8; ++nt)
        #pragma unroll
        for (int i=0; i<4; ++i){
            const int m = mBase + wm*64 + mt*16 + lr + ((i>>1)<<3);
            const int n = nBase + wn*64 + nt*8 + (lk<<1) + (i&1);
            float v = acc[mt][nt][i] + bias[n];
            if (MODE == 0){
                const int bb = m >> 11, t = m & 2047;
                if (n < 2048){
                    const int h = n >> 7, d = n & 127;
                    O0[((size_t)((bb*16+h)*2048 + t))*128 + d] = v;           // Q scratch
                } else if (n < 4096){
                    const int o = n - 2048, h = o >> 7, d = o & 127;
                    O1[((size_t)((bb*16+h)*2048 + t))*128 + d] = v;           // K out
                } else {
                    const int o = n - 4096, h = o >> 7, d = o & 127;
                    O2[((size_t)((bb*16+h)*2048 + t))*128 + d] = v;           // V out
                }
            } else {
                O0[(size_t)m*CDIM + n] = v;
            }
        }
}

// ===================== Fused flash attention (fp16 MMA) =====================
// CTA = (q-tile of 128 rows, bh). 8 warps, warp w owns q rows [16w,16w+16).
// smem: sQh 32KB fp16 | sKh 32KB fp16 | sK32 64KB fp32 landing | sV 64KB fp32.
__global__ void __launch_bounds__(256, 1)
flash_attn(const float* __restrict__ Qg_, const float* __restrict__ Kg_,
           const float* __restrict__ Vg_, __half* __restrict__ Yg)
{
    const int qtile = 15 - blockIdx.x;   // long blocks first
    const int bh    = blockIdx.y;
    const int tid   = threadIdx.x;
    const int lane  = tid & 31, w = tid >> 5;
    const int lr    = lane >> 2, lk = lane & 3;
    const int wrow  = w * 16;

    extern __shared__ unsigned sm[];
    __half*   sQh  = (__half*)sm;                      // 32KB
    __half*   sKh  = (__half*)((char*)sm + 32768);     // 32KB
    unsigned* sK32 = sm + 16384;                       // 64KB fp32 words (offset 65536B)
    float*    sV   = (float*)((char*)sm + 131072);     // 64KB
    const unsigned sb  = (unsigned)__cvta_generic_to_shared(sm);
    const unsigned sKb = sb + 65536;
    const unsigned sVb = sb + 131072;

    const float* Qg = Qg_ + (size_t)bh*SEQ*DK + (size_t)qtile*16384;
    const float* Kg = Kg_ + (size_t)bh*SEQ*DK;
    const float* Vg = Vg_ + (size_t)bh*SEQ*DK;

    // prologue: issue K32(0), V(0); stage Q -> fp16
    #pragma unroll
    for (int i=0;i<16;++i){
        int idx = tid + i*256, r = idx>>5, f = idx&31;
        int fs = (f&24)|((f&7)^(r&7));
        cpa(sKb + (unsigned)(r*128+fs*4)*4u, Kg + r*128 + f*4);
    }
    cpcommit();
    #pragma unroll
    for (int i=0;i<16;++i){
        int idx = tid + i*256, r = idx>>5, f = idx&31;
        int fs = (f&24)|((f&7)^(r&7));
        cpa(sVb + (unsigned)(r*128+fs*4)*4u, Vg + r*128 + f*4);
    }
    cpcommit();
    const float qscale = (float)(1.4426950408889634 / 11.313708498984761); // log2e/sqrt(dk)
    #pragma unroll
    for (int i=0;i<16;++i){
        int idx = tid + i*256, r = idx>>5, f = idx&31;
        float4 v = *(const float4*)(Qg + r*128 + f*4);
        *(uint2*)&sQh[swh(r, 4*f)] =
            make_uint2(packh2(v.x*qscale, v.y*qscale), packh2(v.z*qscale, v.w*qscale));
    }

    float m0=-1e30f, m1=-1e30f, l0=0.f, l1=0.f;
    float O[16][4];
    #pragma unroll
    for (int nt=0; nt<16; ++nt){ O[nt][0]=0.f; O[nt][1]=0.f; O[nt][2]=0.f; O[nt][3]=0.f; }

    for (int j = 0; j <= qtile; ++j){
        cpwait<1>();                       // K32(j) arrived (V(j) may be pending)
        __syncthreads();

        // convert K32(j) -> fp16 sKh
        #pragma unroll
        for (int i=0;i<16;++i){
            int idx = tid + i*256, r = idx>>5, f = idx&31;
            int fs = (f&24)|((f&7)^(r&7));
            uint4 u = *(uint4*)(sK32 + r*128 + fs*4);
            *(uint2*)&sKh[swh(r, 4*f)] =
                make_uint2(packh2(__uint_as_float(u.x), __uint_as_float(u.y)),
                           packh2(__uint_as_float(u.z), __uint_as_float(u.w)));
        }
        __syncthreads();

        if (j < qtile){                    // K32 free: prefetch K(j+1) now (overlaps S+PV)
            const float* Kj = Kg + (size_t)(j+1)*16384;
            #pragma unroll
            for (int i=0;i<16;++i){
                int idx = tid + i*256, r = idx>>5, f = idx&31;
                int fs = (f&24)|((f&7)^(r&7));
                cpa(sKb + (unsigned)(r*128+fs*4)*4u, Kj + r*128 + f*4);
            }
            cpcommit();
        }

        // S = Q K^T  (fp16 MMA, 8 k16 steps)
        float S[16][4];
        #pragma unroll
        for (int nt=0; nt<16; ++nt){ S[nt][0]=0.f; S[nt][1]=0.f; S[nt][2]=0.f; S[nt][3]=0.f; }
        #pragma unroll
        for (int ks=0; ks<8; ++ks){
            const int hk = ks*16 + 2*lk;
            const unsigned a0 = *(const unsigned*)&sQh[swh(wrow+lr,   hk)];
            const unsigned a1 = *(const unsigned*)&sQh[swh(wrow+lr+8, hk)];
            const unsigned a2 = *(const unsigned*)&sQh[swh(wrow+lr,   hk+8)];
            const unsigned a3 = *(const unsigned*)&sQh[swh(wrow+lr+8, hk+8)];
            #pragma unroll
            for (int nt=0; nt<16; ++nt){
                const unsigned b0 = *(const unsigned*)&sKh[swh(nt*8+lr, hk)];
                const unsigned b1 = *(const unsigned*)&sKh[swh(nt*8+lr, hk+8)];
                mma16(S[nt], a0, a1, a2, a3, b0, b1);
            }
        }

        if (j < qtile) cpwait<1>(); else cpwait<0>();   // V(j) done
        __syncthreads();                                // sV visible to all

        // causal mask on diagonal tile
        if (j == qtile){
            #pragma unroll
            for (int nt=0; nt<16; ++nt){
                const int c0 = nt*8 + 2*lk, c1 = c0 + 1;
                const int r0 = wrow + lr,   r1 = r0 + 8;
                if (c0 > r0) S[nt][0] = -1e30f;
                if (c1 > r0) S[nt][1] = -1e30f;
                if (c0 > r1) S[nt][2] = -1e30f;
                if (c1 > r1) S[nt][3] = -1e30f;
            }
        }

        // online softmax (base-2 domain; quad-local reductions)
        float mx0 = -1e30f, mx1 = -1e30f;
        #pragma unroll
        for (int nt=0; nt<16; ++nt){
            mx0 = fmaxf(mx0, fmaxf(S[nt][0], S[nt][1]));
            mx1 = fmaxf(mx1, fmaxf(S[nt][2], S[nt][3]));
        }
        mx0 = fmaxf(mx0, __shfl_xor_sync(0xffffffffu, mx0, 1));
        mx0 = fmaxf(mx0, __shfl_xor_sync(0xffffffffu, mx0, 2));
        mx1 = fmaxf(mx1, __shfl_xor_sync(0xffffffffu, mx1, 1));
        mx1 = fmaxf(mx1, __shfl_xor_sync(0xffffffffu, mx1, 2));
        const float nm0 = fmaxf(m0, mx0), nm1 = fmaxf(m1, mx1);
        const float f0 = ex2f(m0 - nm0), f1 = ex2f(m1 - nm1);
        float s0 = 0.f, s1 = 0.f;
        #pragma unroll
        for (int nt=0; nt<16; ++nt){
            S[nt][0] = ex2f(S[nt][0] - nm0); s0 += S[nt][0];
            S[nt][1] = ex2f(S[nt][1] - nm0); s0 += S[nt][1];
            S[nt][2] = ex2f(S[nt][2] - nm1); s1 += S[nt][2];
            S[nt][3] = ex2f(S[nt][3] - nm1); s1 += S[nt][3];
        }
        s0 += __shfl_xor_sync(0xffffffffu, s0, 1);
        s0 += __shfl_xor_sync(0xffffffffu, s0, 2);
        s1 += __shfl_xor_sync(0xffffffffu, s1, 1);
        s1 += __shfl_xor_sync(0xffffffffu, s1, 2);
        l0 = l0*f0 + s0; l1 = l1*f1 + s1; m0 = nm0; m1 = nm1;
        #pragma unroll
        for (int nt=0; nt<16; ++nt){
            O[nt][0] *= f0; O[nt][1] *= f0; O[nt][2] *= f1; O[nt][3] *= f1;
        }

        // O += P @ V   (P from S regs via the accumulator->A-fragment identity)
        #pragma unroll
        for (int kk=0; kk<8; ++kk){
            const unsigned a0 = packh2(S[2*kk  ][0], S[2*kk  ][1]);
            const unsigned a1 = packh2(S[2*kk  ][2], S[2*kk  ][3]);
            const unsigned a2 = packh2(S[2*kk+1][0], S[2*kk+1][1]);
            const unsigned a3 = packh2(S[2*kk+1][2], S[2*kk+1][3]);
            #pragma unroll
            for (int nt=0; nt<16; ++nt){
                const float v00 = sV[swi(16*kk+2*lk,   nt*8+lr)];
                const float v01 = sV[swi(16*kk+2*lk+1, nt*8+lr)];
                const float v10 = sV[swi(16*kk+2*lk+8, nt*8+lr)];
                const float v11 = sV[swi(16*kk+2*lk+9, nt*8+lr)];
                mma16(O[nt], a0, a1, a2, a3, packh2(v00, v01), packh2(v10, v11));
            }
        }

        __syncthreads();                                // all done reading sV
        if (j < qtile){                                 // prefetch V(j+1)
            const float* Vj = Vg + (size_t)(j+1)*16384;
            #pragma unroll
            for (int i=0;i<16;++i){
                int idx = tid + i*256, r = idx>>5, f = idx&31;
                int fs = (f&24)|((f&7)^(r&7));
                cpa(sVb + (unsigned)(r*128+fs*4)*4u, Vj + r*128 + f*4);
            }
            cpcommit();
        }
    }

    // epilogue: normalize and write fp16 Y[b, t, h*128 + d] (feeds proj GEMM)
    const float inv0 = 1.f / l0, inv1 = 1.f / l1;
    const int rg = qtile*128 + wrow + lr;
    const size_t base = ((size_t)(bh>>4)*SEQ + rg)*CDIM + (bh&15)*DK;
    #pragma unroll
    for (int nt=0; nt<16; ++nt){
        *(unsigned*)(Yg + base + nt*8 + 2*lk) = packh2(O[nt][0]*inv0, O[nt][1]*inv0);
        *(unsigned*)(Yg + base + (size_t)8*CDIM + nt*8 + 2*lk) = packh2(O[nt][2]*inv1, O[nt][3]*inv1);
    }
}

extern "C" void kernel_launch(void* const* d_in, const int* in_sizes, int n_in,
                              void* d_out, int out_size)
{
    const float* x      = (const float*)d_in[0];
    const float* w_attn = (const float*)d_in[1];
    const float* b_attn = (const float*)d_in[2];
    const float* w_proj = (const float*)d_in[3];
    const float* b_proj = (const float*)d_in[4];

    float* yOut = (float*)d_out;
    float* kOut = yOut + (size_t)BTC;
    float* vOut = yOut + (size_t)2*BTC;

    float *Q; __half *Xh, *WAh, *WPh, *Yh;
    cudaGetSymbolAddress((void**)&Q,   g_Q);
    cudaGetSymbolAddress((void**)&Xh,  g_Xh);
    cudaGetSymbolAddress((void**)&WAh, g_WAh);
    cudaGetSymbolAddress((void**)&WPh, g_WPh);
    cudaGetSymbolAddress((void**)&Yh,  g_Yh);

    const int smemG = 196608;   // 4 stages x 48KB
    const int smemF = 196608;
    cudaFuncSetAttribute(gemm_h<0>,  cudaFuncAttributeMaxDynamicSharedMemorySize, smemG);
    cudaFuncSetAttribute(gemm_h<1>,  cudaFuncAttributeMaxDynamicSharedMemorySize, smemG);
    cudaFuncSetAttribute(flash_attn, cudaFuncAttributeMaxDynamicSharedMemorySize, smemF);

    // 0) one-time fp16 conversions
    cvt_f16<<<BTC/2048,           256>>>(x,      Xh);
    cvt_f16<<<3*CDIM*CDIM/2048,   256>>>(w_attn, WAh);
    cvt_f16<<<CDIM*CDIM/2048,     256>>>(w_proj, WPh);

    // 1) QKV = x @ w_attn^T + b_attn   (M=8192, N=6144, K=2048)
    gemm_h<0><<<dim3(24,64), 256, smemG>>>(Xh, WAh, b_attn, Q, kOut, vOut);

    // 2) fused flash attention: Y = softmax(QK^T/sqrt(dk), causal) V  -> fp16 Yh
    flash_attn<<<dim3(16,64), 256, smemF>>>(Q, kOut, vOut, Yh);

    // 3) y = Y @ w_proj^T + b_proj   (M=8192, N=2048, K=2048)
    gemm_h<1><<<dim3(8,64), 256, smemG>>>(Yh, WPh, b_proj, yOut, nullptr, nullptr);
}

// round 6
// speedup vs baseline: 4.1606x; 1.4643x over previous
#include <cuda_runtime.h>
#include <cuda_fp16.h>
#include <cstdint>

#define BATCH 4
#define SEQ   2048
#define CDIM  2048
#define NH    16
#define DK    128
#define BH    (BATCH*NH)          /* 64  */
#define BTC   (BATCH*SEQ*CDIM)    /* 16777216 */

// Scratch (static device arrays: sanctioned scratch mechanism, no allocs)
__device__ __align__(16) __half g_Xh [(size_t)BTC];         // x fp16      (32 MB)
__device__ __align__(16) __half g_WAh[(size_t)3*CDIM*CDIM]; // w_attn fp16 (24 MB)
__device__ __align__(16) __half g_WPh[(size_t)CDIM*CDIM];   // w_proj fp16 ( 8 MB)
__device__ __align__(16) __half g_Qh [(size_t)BH*SEQ*DK];   // Q fp16 [b,h,t,d]
__device__ __align__(16) __half g_Kh [(size_t)BH*SEQ*DK];   // K fp16 [b,h,t,d]
__device__ __align__(16) __half g_Vh [(size_t)BH*SEQ*DK];   // V fp16 [b,h,t,d]
__device__ __align__(16) __half g_Yh [(size_t)BTC];         // attn out fp16 [b,t,c]

__device__ __forceinline__ unsigned packh2(float lo, float hi){
    unsigned d; asm("cvt.rn.f16x2.f32 %0, %1, %2;" : "=r"(d) : "f"(hi), "f"(lo)); return d;
}
__device__ __forceinline__ float ex2f(float x){
    float y; asm("ex2.approx.f32 %0, %1;" : "=f"(y) : "f"(x)); return y;
}
__device__ __forceinline__ void mma16(float* c, unsigned a0, unsigned a1, unsigned a2,
                                      unsigned a3, unsigned b0, unsigned b1){
    asm volatile("mma.sync.aligned.m16n8k16.row.col.f32.f16.f16.f32 "
        "{%0,%1,%2,%3}, {%4,%5,%6,%7}, {%8,%9}, {%0,%1,%2,%3};\n"
        : "+f"(c[0]), "+f"(c[1]), "+f"(c[2]), "+f"(c[3])
        : "r"(a0), "r"(a1), "r"(a2), "r"(a3), "r"(b0), "r"(b1));
}
__device__ __forceinline__ void ldsm4(unsigned* r, unsigned addr){
    asm volatile("ldmatrix.sync.aligned.m8n8.x4.shared.b16 {%0,%1,%2,%3}, [%4];"
        : "=r"(r[0]), "=r"(r[1]), "=r"(r[2]), "=r"(r[3]) : "r"(addr));
}
__device__ __forceinline__ void ldsm4t(unsigned* r, unsigned addr){
    asm volatile("ldmatrix.sync.aligned.m8n8.x4.trans.shared.b16 {%0,%1,%2,%3}, [%4];"
        : "=r"(r[0]), "=r"(r[1]), "=r"(r[2]), "=r"(r[3]) : "r"(addr));
}
__device__ __forceinline__ void cpa(unsigned dst, const void* src){
    asm volatile("cp.async.cg.shared.global [%0], [%1], 16;\n" :: "r"(dst), "l"(src));
}
__device__ __forceinline__ void cpcommit(){ asm volatile("cp.async.commit_group;\n"); }
template<int N> __device__ __forceinline__ void cpwait(){
    asm volatile("cp.async.wait_group %0;\n" :: "n"(N));
}
// half index into a [rows][128 halfs] fp16 tile (256B rows), 16B-group xor swizzle
__device__ __forceinline__ int swh(int r, int h){
    int g = h >> 3;
    return r*128 + (((g & 8) | ((g & 7) ^ (r & 7))) << 3) + (h & 7);
}

// ===================== fp32 -> fp16 conversion (8 elems/thread) =====================
__global__ void __launch_bounds__(256)
cvt_f16(const float* __restrict__ in, __half* __restrict__ out)
{
    const size_t i = ((size_t)blockIdx.x*256 + threadIdx.x)*8;
    float4 a = *(const float4*)(in + i);
    float4 b = *(const float4*)(in + i + 4);
    uint4 o = make_uint4(packh2(a.x,a.y), packh2(a.z,a.w), packh2(b.x,b.y), packh2(b.z,b.w));
    *(uint4*)(out + i) = o;
}

// ===================== fp16 GEMM: 128x128 tile, 3-stage cp.async, 2 CTA/SM ==========
// D = A[128rows,2048] @ B[128rows,2048]^T + bias. 8 warps as 4(m)x2(n), warp 32x64.
// MODE 0: QKV -> Q fp16 scratch / K fp32+fp16 / V fp32+fp16.  MODE 1: proj -> fp32.
template<int MODE>
__global__ void __launch_bounds__(256, 2)
gemm_h(const __half* __restrict__ Ag, const __half* __restrict__ Bg,
       const float* __restrict__ bias,
       float* __restrict__ F0, float* __restrict__ F1, float* __restrict__ F2,
       __half* __restrict__ H0, __half* __restrict__ H1, __half* __restrict__ H2)
{
    extern __shared__ __half sh[];   // 3 stages x (A 128x64 | B 128x64) = 96KB
    const unsigned sb = (unsigned)__cvta_generic_to_shared(sh);
    const int tid  = threadIdx.x;
    const int lane = tid & 31, w = tid >> 5;
    const int wm = w >> 1, wn = w & 1;
    const int lr = lane >> 2, lk = lane & 3;
    const int mBase = blockIdx.y*128, nBase = blockIdx.x*128;

    const __half* A = Ag + (size_t)mBase*2048;
    const __half* B = Bg + (size_t)nBase*2048;

    const int l15 = lane & 15;
    int aRow[2], bRow[4];
    #pragma unroll
    for (int mt=0; mt<2; ++mt) aRow[mt] = wm*32 + mt*16 + l15;
    #pragma unroll
    for (int np=0; np<4; ++np) bRow[np] = wn*64 + np*16 + ((lane>>4)<<3) + (lane&7);
    const int gA = lane >> 4, gB = (lane >> 3) & 1;

    float acc[2][8][4];
    #pragma unroll
    for (int mt=0; mt<2; ++mt)
      #pragma unroll
      for (int nt=0; nt<8; ++nt)
        #pragma unroll
        for (int i=0; i<4; ++i) acc[mt][nt][i] = 0.f;

    auto issue = [&](int slot, int kt){
        const unsigned st = sb + (unsigned)slot*32768u;
        #pragma unroll
        for (int i=0;i<4;++i){
            int idx = tid + i*256, r = idx>>3, g = idx&7;
            cpa(st + (unsigned)(r*128) + (unsigned)((g^(r&7))<<4),
                A + (size_t)r*2048 + kt*64 + g*8);
        }
        #pragma unroll
        for (int i=0;i<4;++i){
            int idx = tid + i*256, r = idx>>3, g = idx&7;
            cpa(st + 16384u + (unsigned)(r*128) + (unsigned)((g^(r&7))<<4),
                B + (size_t)r*2048 + kt*64 + g*8);
        }
    };

    issue(0,0); cpcommit();
    issue(1,1); cpcommit();

    const int KT = 32;
    for (int kt=0; kt<KT; ++kt){
        cpwait<1>();
        __syncthreads();
        const unsigned stA = sb + (unsigned)(kt%3)*32768u;
        const unsigned stB = stA + 16384u;
        #pragma unroll
        for (int ks=0; ks<4; ++ks){
            unsigned af[2][4], bf[4][4];
            #pragma unroll
            for (int mt=0; mt<2; ++mt)
                ldsm4(af[mt], stA + (unsigned)(aRow[mt]*128) + (unsigned)(((2*ks+gA)^(aRow[mt]&7))<<4));
            #pragma unroll
            for (int np=0; np<4; ++np)
                ldsm4(bf[np], stB + (unsigned)(bRow[np]*128) + (unsigned)(((2*ks+gB)^(bRow[np]&7))<<4));
            #pragma unroll
            for (int mt=0; mt<2; ++mt)
                #pragma unroll
                for (int nt=0; nt<8; ++nt)
                    mma16(acc[mt][nt], af[mt][0], af[mt][1], af[mt][2], af[mt][3],
                          bf[nt>>1][2*(nt&1)], bf[nt>>1][2*(nt&1)+1]);
        }
        if (kt+2 < KT) issue((kt+2)%3, kt+2);
        cpcommit();
    }

    // epilogue: paired stores (col, col+1 contiguous)
    #pragma unroll
    for (int mt=0; mt<2; ++mt)
      #pragma unroll
      for (int nt=0; nt<8; ++nt){
        const int row0 = mBase + wm*32 + mt*16 + lr;
        const int col  = nBase + wn*64 + nt*8 + 2*lk;
        float2 bv = *(const float2*)(bias + col);
        const float v00 = acc[mt][nt][0] + bv.x, v01 = acc[mt][nt][1] + bv.y;
        const float v10 = acc[mt][nt][2] + bv.x, v11 = acc[mt][nt][3] + bv.y;
        #pragma unroll
        for (int half=0; half<2; ++half){
            const int m = row0 + half*8;
            const float v0 = half ? v10 : v00, v1 = half ? v11 : v01;
            if (MODE == 0){
                const int bb = m >> 11, t = m & 2047;
                if (col < 2048){
                    const size_t idx = ((size_t)((bb*16 + (col>>7))*2048 + t))*128 + (col & 127);
                    *(unsigned*)(H0 + idx) = packh2(v0, v1);                 // Q fp16
                } else if (col < 4096){
                    const int o = col - 2048;
                    const size_t idx = ((size_t)((bb*16 + (o>>7))*2048 + t))*128 + (o & 127);
                    *(float2*)(F1 + idx) = make_float2(v0, v1);              // K fp32 out
                    *(unsigned*)(H1 + idx) = packh2(v0, v1);                 // K fp16
                } else {
                    const int o = col - 4096;
                    const size_t idx = ((size_t)((bb*16 + (o>>7))*2048 + t))*128 + (o & 127);
                    *(float2*)(F2 + idx) = make_float2(v0, v1);              // V fp32 out
                    *(unsigned*)(H2 + idx) = packh2(v0, v1);                 // V fp16
                }
            } else {
                *(float2*)(F0 + (size_t)m*CDIM + col) = make_float2(v0, v1);
            }
        }
      }
}

// ===================== Fused flash attention (all-fp16 operands, ldmatrix) ==========
// CTA = (q-tile 128 rows, bh). 8 warps; warp w owns q rows [16w,16w+16).
// smem: sQ 32KB | sK[2] 32KB each | sV[2] 32KB each = 160KB. Double-buffered KV stream.
__global__ void __launch_bounds__(256, 1)
flash_attn(const __half* __restrict__ Qg_, const __half* __restrict__ Kg_,
           const __half* __restrict__ Vg_, __half* __restrict__ Yg)
{
    const int qtile = 15 - blockIdx.x;   // long blocks first
    const int bh    = blockIdx.y;
    const int tid   = threadIdx.x;
    const int lane  = tid & 31, w = tid >> 5;
    const int lr    = lane >> 2, lk = lane & 3;
    const int wrow  = w * 16;

    extern __shared__ __half smh[];
    __half* sQh = smh;
    const unsigned sb  = (unsigned)__cvta_generic_to_shared(smh);
    const unsigned sbK = sb + 32768u;     // two 32KB K slots
    const unsigned sbV = sb + 98304u;     // two 32KB V slots

    const __half* Qg = Qg_ + (size_t)bh*SEQ*DK + (size_t)qtile*16384;
    const __half* Kg = Kg_ + (size_t)bh*SEQ*DK;
    const __half* Vg = Vg_ + (size_t)bh*SEQ*DK;

    auto issueKV = [&](int j){
        if (j <= qtile){
            const __half* Kj = Kg + (size_t)j*16384;
            const __half* Vj = Vg + (size_t)j*16384;
            const unsigned dK = sbK + (unsigned)(j&1)*32768u;
            const unsigned dV = sbV + (unsigned)(j&1)*32768u;
            #pragma unroll
            for (int i=0;i<8;++i){
                int idx = tid + i*256, r = idx>>4, g = idx&15;
                unsigned sw = (unsigned)((g&8)|((g&7)^(r&7)));
                cpa(dK + (unsigned)(r*256) + sw*16u, Kj + r*128 + g*8);
                cpa(dV + (unsigned)(r*256) + sw*16u, Vj + r*128 + g*8);
            }
        }
        cpcommit();
    };
    issueKV(0);
    issueKV(1);

    // stage Q (fp16 global -> swizzled smem)
    #pragma unroll
    for (int i=0;i<8;++i){
        int idx = tid + i*256, r = idx>>4, g = idx&15;
        int sw = (g&8)|((g&7)^(r&7));
        *(uint4*)&sQh[r*128 + sw*8] = *(const uint4*)(Qg + r*128 + g*8);
    }
    __syncthreads();

    // hoist Q fragments (reused across all kv tiles)
    unsigned qf[8][4];
    #pragma unroll
    for (int ks=0;ks<8;++ks){
        const int row = wrow + (lane & 15);
        const int h   = ks*16 + (lane>>4)*8;
        ldsm4(qf[ks], sb + 2u*(unsigned)swh(row, h));
    }

    float m0=-1e30f, m1=-1e30f, l0=0.f, l1=0.f;
    float O[16][4];
    #pragma unroll
    for (int nt=0; nt<16; ++nt){ O[nt][0]=0.f; O[nt][1]=0.f; O[nt][2]=0.f; O[nt][3]=0.f; }

    const float c = 0.1275310112f;   // log2e / sqrt(128)

    for (int j = 0; j <= qtile; ++j){
        cpwait<1>();
        __syncthreads();
        const unsigned bK = sbK + (unsigned)(j&1)*32768u;
        const unsigned bV = sbV + (unsigned)(j&1)*32768u;

        // S = Q K^T
        float S[16][4];
        #pragma unroll
        for (int nt=0; nt<16; ++nt){ S[nt][0]=0.f; S[nt][1]=0.f; S[nt][2]=0.f; S[nt][3]=0.f; }
        #pragma unroll
        for (int ks=0; ks<8; ++ks){
            #pragma unroll
            for (int np=0; np<8; ++np){
                unsigned kf[4];
                const int row = np*16 + ((lane>>4)<<3) + (lane&7);
                const int h   = ks*16 + ((lane>>3)&1)*8;
                ldsm4(kf, bK + 2u*(unsigned)swh(row, h));
                mma16(S[2*np],   qf[ks][0],qf[ks][1],qf[ks][2],qf[ks][3], kf[0], kf[1]);
                mma16(S[2*np+1], qf[ks][0],qf[ks][1],qf[ks][2],qf[ks][3], kf[2], kf[3]);
            }
        }

        // scale into base-2 domain
        #pragma unroll
        for (int nt=0; nt<16; ++nt){
            S[nt][0]*=c; S[nt][1]*=c; S[nt][2]*=c; S[nt][3]*=c;
        }

        // causal mask on diagonal tile
        if (j == qtile){
            #pragma unroll
            for (int nt=0; nt<16; ++nt){
                const int c0 = nt*8 + 2*lk, c1 = c0 + 1;
                const int r0 = wrow + lr,   r1 = r0 + 8;
                if (c0 > r0) S[nt][0] = -1e30f;
                if (c1 > r0) S[nt][1] = -1e30f;
                if (c0 > r1) S[nt][2] = -1e30f;
                if (c1 > r1) S[nt][3] = -1e30f;
            }
        }

        // online softmax (quad-local reductions)
        float mx0 = -1e30f, mx1 = -1e30f;
        #pragma unroll
        for (int nt=0; nt<16; ++nt){
            mx0 = fmaxf(mx0, fmaxf(S[nt][0], S[nt][1]));
            mx1 = fmaxf(mx1, fmaxf(S[nt][2], S[nt][3]));
        }
        mx0 = fmaxf(mx0, __shfl_xor_sync(0xffffffffu, mx0, 1));
        mx0 = fmaxf(mx0, __shfl_xor_sync(0xffffffffu, mx0, 2));
        mx1 = fmaxf(mx1, __shfl_xor_sync(0xffffffffu, mx1, 1));
        mx1 = fmaxf(mx1, __shfl_xor_sync(0xffffffffu, mx1, 2));
        const float nm0 = fmaxf(m0, mx0), nm1 = fmaxf(m1, mx1);
        const float f0 = ex2f(m0 - nm0), f1 = ex2f(m1 - nm1);
        float s0 = 0.f, s1 = 0.f;
        #pragma unroll
        for (int nt=0; nt<16; ++nt){
            S[nt][0] = ex2f(S[nt][0] - nm0); s0 += S[nt][0];
            S[nt][1] = ex2f(S[nt][1] - nm0); s0 += S[nt][1];
            S[nt][2] = ex2f(S[nt][2] - nm1); s1 += S[nt][2];
            S[nt][3] = ex2f(S[nt][3] - nm1); s1 += S[nt][3];
        }
        s0 += __shfl_xor_sync(0xffffffffu, s0, 1);
        s0 += __shfl_xor_sync(0xffffffffu, s0, 2);
        s1 += __shfl_xor_sync(0xffffffffu, s1, 1);
        s1 += __shfl_xor_sync(0xffffffffu, s1, 2);
        l0 = l0*f0 + s0; l1 = l1*f1 + s1; m0 = nm0; m1 = nm1;
        #pragma unroll
        for (int nt=0; nt<16; ++nt){
            O[nt][0] *= f0; O[nt][1] *= f0; O[nt][2] *= f1; O[nt][3] *= f1;
        }

        // O += P @ V   (P from S regs; V b-frags via ldmatrix.trans)
        #pragma unroll
        for (int kk=0; kk<8; ++kk){
            const unsigned a0 = packh2(S[2*kk  ][0], S[2*kk  ][1]);
            const unsigned a1 = packh2(S[2*kk  ][2], S[2*kk  ][3]);
            const unsigned a2 = packh2(S[2*kk+1][0], S[2*kk+1][1]);
            const unsigned a3 = packh2(S[2*kk+1][2], S[2*kk+1][3]);
            #pragma unroll
            for (int np=0; np<8; ++np){
                unsigned vf[4];
                const int row = kk*16 + ((lane>>3)&1)*8 + (lane&7);
                const int d   = np*16 + ((lane>>4)<<3);
                ldsm4t(vf, bV + 2u*(unsigned)swh(row, d));
                mma16(O[2*np],   a0,a1,a2,a3, vf[0], vf[1]);
                mma16(O[2*np+1], a0,a1,a2,a3, vf[2], vf[3]);
            }
        }

        __syncthreads();          // all warps done with slot (j&1)
        issueKV(j+2);             // refill freed slot (empty commit past end)
    }

    // epilogue: normalize, write fp16 Y[b, t, h*128 + d]
    const float inv0 = 1.f / l0, inv1 = 1.f / l1;
    const int rg = qtile*128 + wrow + lr;
    const size_t base = ((size_t)(bh>>4)*SEQ + rg)*CDIM + (bh&15)*DK;
    #pragma unroll
    for (int nt=0; nt<16; ++nt){
        *(unsigned*)(Yg + base + nt*8 + 2*lk) = packh2(O[nt][0]*inv0, O[nt][1]*inv0);
        *(unsigned*)(Yg + base + (size_t)8*CDIM + nt*8 + 2*lk) = packh2(O[nt][2]*inv1, O[nt][3]*inv1);
    }
}

extern "C" void kernel_launch(void* const* d_in, const int* in_sizes, int n_in,
                              void* d_out, int out_size)
{
    const float* x      = (const float*)d_in[0];
    const float* w_attn = (const float*)d_in[1];
    const float* b_attn = (const float*)d_in[2];
    const float* w_proj = (const float*)d_in[3];
    const float* b_proj = (const float*)d_in[4];

    float* yOut = (float*)d_out;
    float* kOut = yOut + (size_t)BTC;
    float* vOut = yOut + (size_t)2*BTC;

    __half *Xh, *WAh, *WPh, *Qh, *Kh, *Vh, *Yh;
    cudaGetSymbolAddress((void**)&Xh,  g_Xh);
    cudaGetSymbolAddress((void**)&WAh, g_WAh);
    cudaGetSymbolAddress((void**)&WPh, g_WPh);
    cudaGetSymbolAddress((void**)&Qh,  g_Qh);
    cudaGetSymbolAddress((void**)&Kh,  g_Kh);
    cudaGetSymbolAddress((void**)&Vh,  g_Vh);
    cudaGetSymbolAddress((void**)&Yh,  g_Yh);

    const int smemG = 98304;    // 3 stages x 32KB
    const int smemF = 163840;   // Q 32K + K 2x32K + V 2x32K
    cudaFuncSetAttribute(gemm_h<0>,  cudaFuncAttributeMaxDynamicSharedMemorySize, smemG);
    cudaFuncSetAttribute(gemm_h<1>,  cudaFuncAttributeMaxDynamicSharedMemorySize, smemG);
    cudaFuncSetAttribute(flash_attn, cudaFuncAttributeMaxDynamicSharedMemorySize, smemF);

    // 0) one-time fp16 conversions
    cvt_f16<<<BTC/2048,         256>>>(x,      Xh);
    cvt_f16<<<3*CDIM*CDIM/2048, 256>>>(w_attn, WAh);
    cvt_f16<<<CDIM*CDIM/2048,   256>>>(w_proj, WPh);

    // 1) QKV = x @ w_attn^T + b_attn  (M=8192, N=6144, K=2048)
    gemm_h<0><<<dim3(48,64), 256, smemG>>>(Xh, WAh, b_attn,
                                           nullptr, kOut, vOut, Qh, Kh, Vh);

    // 2) fused flash attention: Y = softmax(QK^T/sqrt(dk), causal) V  -> fp16 Yh
    flash_attn<<<dim3(16,64), 256, smemF>>>(Qh, Kh, Vh, Yh);

    // 3) y = Y @ w_proj^T + b_proj   (M=8192, N=2048, K=2048)
    gemm_h<1><<<dim3(16,64), 256, smemG>>>(Yh, WPh, b_proj,
                                           yOut, nullptr, nullptr, nullptr, nullptr, nullptr);
}